// round 4
// baseline (speedup 1.0000x reference)
#include <cuda_runtime.h>
#include <cstdint>

// ---------------- problem constants ----------------
#define BATCH 2
#define SEQ   2048
#define D_IN  512
#define D_MODEL 1024
#define NHEAD 16
#define HEADDIM 64
#define MROWS (BATCH*SEQ)   // 4096

// ---------------- scratch (allocation-free: __device__ globals) ----------------
__device__ float g_e  [MROWS * D_MODEL];
__device__ float g_q  [MROWS * D_MODEL];
__device__ float g_k  [MROWS * D_MODEL];
__device__ float g_v  [MROWS * D_MODEL];
__device__ float g_ctx[MROWS * D_MODEL];
__device__ float g_mha[MROWS * D_MODEL];
__device__ float g_h1 [MROWS * D_MODEL];

// ============================================================================
// Tiled SGEMM: C[M,N] = A[M,K] @ W[K,N] + bias[N]  (+ optional ReLU, + optional residual)
// BM=128, BN=128, BK=16, 256 threads, 8x8 register tile per thread.
// M,N,K are all multiples of the tile sizes here (4096 / 1024 / {512,1024}).
// ============================================================================
__global__ void __launch_bounds__(256)
sgemm_bias_kernel(const float* __restrict__ A, const float* __restrict__ W,
                  const float* __restrict__ bias, const float* __restrict__ res,
                  float* __restrict__ C, int M, int N, int K, int relu)
{
    __shared__ float As[16][128];   // A tile transposed: As[k][m]
    __shared__ float Bs[16][128];   // B tile: Bs[k][n]

    const int tid = threadIdx.x;
    const int m0 = blockIdx.y * 128;
    const int n0 = blockIdx.x * 128;
    const int tm = tid >> 4;        // 0..15
    const int tn = tid & 15;        // 0..15

    float acc[8][8];
#pragma unroll
    for (int i = 0; i < 8; i++)
#pragma unroll
        for (int j = 0; j < 8; j++) acc[i][j] = 0.f;

    // A-tile load mapping: 128 rows x 16 cols = 512 float4; 2 per thread
    const int arow0 = tid >> 2;          // 0..63
    const int ac4   = (tid & 3) << 2;    // 0,4,8,12
    // B-tile load mapping: 16 rows x 128 cols = 512 float4; 2 per thread
    const int brow0 = tid >> 5;          // 0..7
    const int bc4   = (tid & 31) << 2;   // 0..124

    for (int k0 = 0; k0 < K; k0 += 16) {
#pragma unroll
        for (int s = 0; s < 2; s++) {
            const int row = arow0 + s * 64;
            const float4 a = *(const float4*)&A[(size_t)(m0 + row) * K + k0 + ac4];
            As[ac4 + 0][row] = a.x;
            As[ac4 + 1][row] = a.y;
            As[ac4 + 2][row] = a.z;
            As[ac4 + 3][row] = a.w;
        }
#pragma unroll
        for (int s = 0; s < 2; s++) {
            const int row = brow0 + s * 8;
            *(float4*)&Bs[row][bc4] =
                *(const float4*)&W[(size_t)(k0 + row) * N + n0 + bc4];
        }
        __syncthreads();

#pragma unroll
        for (int k = 0; k < 16; k++) {
            float a[8], b[8];
            *(float4*)&a[0] = *(const float4*)&As[k][tm * 8];
            *(float4*)&a[4] = *(const float4*)&As[k][tm * 8 + 4];
            *(float4*)&b[0] = *(const float4*)&Bs[k][tn * 8];
            *(float4*)&b[4] = *(const float4*)&Bs[k][tn * 8 + 4];
#pragma unroll
            for (int i = 0; i < 8; i++)
#pragma unroll
                for (int j = 0; j < 8; j++)
                    acc[i][j] = fmaf(a[i], b[j], acc[i][j]);
        }
        __syncthreads();
    }

    // epilogue: bias (+relu) (+residual)
#pragma unroll
    for (int i = 0; i < 8; i++) {
        const int m = m0 + tm * 8 + i;
#pragma unroll
        for (int j = 0; j < 8; j += 4) {
            const int n = n0 + tn * 8 + j;
            float4 o;
            o.x = acc[i][j + 0] + bias[n + 0];
            o.y = acc[i][j + 1] + bias[n + 1];
            o.z = acc[i][j + 2] + bias[n + 2];
            o.w = acc[i][j + 3] + bias[n + 3];
            if (relu) {
                o.x = fmaxf(o.x, 0.f); o.y = fmaxf(o.y, 0.f);
                o.z = fmaxf(o.z, 0.f); o.w = fmaxf(o.w, 0.f);
            }
            if (res) {
                const float4 r = *(const float4*)&res[(size_t)m * N + n];
                o.x += r.x; o.y += r.y; o.z += r.z; o.w += r.w;
            }
            *(float4*)&C[(size_t)m * N + n] = o;
        }
    }
}

// ============================================================================
// Flash attention (fp32, non-causal). One CTA = 64 query rows of one (b,h).
// 8 warps, warp handles 8 query rows; lane owns cols {lane, lane+32}.
// Online softmax with warp shuffles; K/V tiles of 64 rows in padded smem.
// ============================================================================
#define ATTN_SMEM (4 * 64 * 65 * sizeof(float))

__global__ void __launch_bounds__(256)
attn_kernel(const float* __restrict__ Q, const float* __restrict__ K,
            const float* __restrict__ V, float* __restrict__ O)
{
    extern __shared__ float sm[];
    float (*Qs)[65] = (float(*)[65])(sm);
    float (*Ks)[65] = (float(*)[65])(sm + 64 * 65);
    float (*Vs)[65] = (float(*)[65])(sm + 2 * 64 * 65);
    float (*Ps)[65] = (float(*)[65])(sm + 3 * 64 * 65);

    const int tid  = threadIdx.x;
    const int warp = tid >> 5;
    const int lane = tid & 31;
    const int q0   = blockIdx.x * 64;
    const int bh   = blockIdx.y;
    const int b    = bh >> 4;          // / NHEAD
    const int h    = bh & (NHEAD - 1);
    const size_t base = (size_t)b * SEQ * D_MODEL + (size_t)h * HEADDIM;
    const float scale = 0.125f;        // 1/sqrt(64)

    // load Q tile (64x64): 1024 float4 / 256 thr = 4 each
#pragma unroll
    for (int s = 0; s < 4; s++) {
        const int id = tid + s * 256;
        const int r = id >> 4;
        const int c = (id & 15) << 2;
        const float4 t = *(const float4*)&Q[base + (size_t)(q0 + r) * D_MODEL + c];
        Qs[r][c] = t.x; Qs[r][c + 1] = t.y; Qs[r][c + 2] = t.z; Qs[r][c + 3] = t.w;
    }

    const int r0 = warp * 8;
    float m_r[8], l_r[8], o0[8], o1[8];
#pragma unroll
    for (int r = 0; r < 8; r++) { m_r[r] = -1e30f; l_r[r] = 0.f; o0[r] = 0.f; o1[r] = 0.f; }

    for (int kv0 = 0; kv0 < SEQ; kv0 += 64) {
        // load K/V tiles (each 64x64)
#pragma unroll
        for (int s = 0; s < 4; s++) {
            const int id = tid + s * 256;
            const int r = id >> 4;
            const int c = (id & 15) << 2;
            const size_t g = base + (size_t)(kv0 + r) * D_MODEL + c;
            const float4 kt = *(const float4*)&K[g];
            Ks[r][c] = kt.x; Ks[r][c + 1] = kt.y; Ks[r][c + 2] = kt.z; Ks[r][c + 3] = kt.w;
            const float4 vt = *(const float4*)&V[g];
            Vs[r][c] = vt.x; Vs[r][c + 1] = vt.y; Vs[r][c + 2] = vt.z; Vs[r][c + 3] = vt.w;
        }
        __syncthreads();

        // S tile = Q K^T : lane owns score cols {lane, lane+32} for 8 rows
        float s0[8], s1[8];
#pragma unroll
        for (int r = 0; r < 8; r++) { s0[r] = 0.f; s1[r] = 0.f; }
#pragma unroll 8
        for (int d = 0; d < 64; d++) {
            const float k0v = Ks[lane][d];        // stride-65 rows: conflict-free
            const float k1v = Ks[lane + 32][d];
#pragma unroll
            for (int r = 0; r < 8; r++) {
                const float qv = Qs[r0 + r][d];   // broadcast
                s0[r] = fmaf(qv, k0v, s0[r]);
                s1[r] = fmaf(qv, k1v, s1[r]);
            }
        }

        // online softmax per row (warp-level)
#pragma unroll
        for (int r = 0; r < 8; r++) {
            float sv0 = s0[r] * scale;
            float sv1 = s1[r] * scale;
            float mx = fmaxf(sv0, sv1);
#pragma unroll
            for (int off = 16; off; off >>= 1)
                mx = fmaxf(mx, __shfl_xor_sync(0xffffffffu, mx, off));
            const float mnew  = fmaxf(m_r[r], mx);
            const float alpha = __expf(m_r[r] - mnew);
            const float p0 = __expf(sv0 - mnew);
            const float p1 = __expf(sv1 - mnew);
            float sum = p0 + p1;
#pragma unroll
            for (int off = 16; off; off >>= 1)
                sum += __shfl_xor_sync(0xffffffffu, sum, off);
            l_r[r] = l_r[r] * alpha + sum;
            m_r[r] = mnew;
            o0[r] *= alpha;
            o1[r] *= alpha;
            Ps[r0 + r][lane]      = p0;
            Ps[r0 + r][lane + 32] = p1;
        }
        __syncwarp();   // Ps rows are warp-private: warp sync suffices

        // O += P @ V : lane owns out cols {lane, lane+32}
#pragma unroll 8
        for (int c = 0; c < 64; c++) {
            const float v0 = Vs[c][lane];
            const float v1 = Vs[c][lane + 32];
#pragma unroll
            for (int r = 0; r < 8; r++) {
                const float p = Ps[r0 + r][c];    // broadcast
                o0[r] = fmaf(p, v0, o0[r]);
                o1[r] = fmaf(p, v1, o1[r]);
            }
        }
        __syncthreads();  // protect Ks/Vs before next tile load
    }

    // normalize + write ctx
#pragma unroll
    for (int r = 0; r < 8; r++) {
        const float inv = 1.f / l_r[r];
        const size_t g = base + (size_t)(q0 + r0 + r) * D_MODEL;
        O[g + lane]      = o0[r] * inv;
        O[g + lane + 32] = o1[r] * inv;
    }
}

// ============================================================================
// kernel_launch: full transformer block as a kernel sequence (graph-capturable)
// ============================================================================
extern "C" void kernel_launch(void* const* d_in, const int* in_sizes, int n_in,
                              void* d_out, int out_size)
{
    (void)in_sizes; (void)n_in; (void)out_size;

    const float* x  = (const float*)d_in[0];
    const float* We = (const float*)d_in[1];
    const float* be = (const float*)d_in[2];
    const float* Wq = (const float*)d_in[3];
    const float* bq = (const float*)d_in[4];
    const float* Wk = (const float*)d_in[5];
    const float* bk = (const float*)d_in[6];
    const float* Wv = (const float*)d_in[7];
    const float* bv = (const float*)d_in[8];
    const float* W0 = (const float*)d_in[9];
    const float* b0 = (const float*)d_in[10];
    const float* W1 = (const float*)d_in[11];
    const float* b1 = (const float*)d_in[12];
    const float* W2 = (const float*)d_in[13];
    const float* b2 = (const float*)d_in[14];
    float* out = (float*)d_out;

    float *e, *q, *k, *v, *ctx, *mha, *h1;
    cudaGetSymbolAddress((void**)&e,   g_e);
    cudaGetSymbolAddress((void**)&q,   g_q);
    cudaGetSymbolAddress((void**)&k,   g_k);
    cudaGetSymbolAddress((void**)&v,   g_v);
    cudaGetSymbolAddress((void**)&ctx, g_ctx);
    cudaGetSymbolAddress((void**)&mha, g_mha);
    cudaGetSymbolAddress((void**)&h1,  g_h1);

    cudaFuncSetAttribute(attn_kernel,
                         cudaFuncAttributeMaxDynamicSharedMemorySize,
                         (int)ATTN_SMEM);

    const dim3 gb(D_MODEL / 128, MROWS / 128);   // (8, 32)

    // e = x @ We + be
    sgemm_bias_kernel<<<gb, 256>>>(x, We, be, nullptr, e, MROWS, D_MODEL, D_IN, 0);
    // q/k/v = e @ W{q,k,v} + b
    sgemm_bias_kernel<<<gb, 256>>>(e, Wq, bq, nullptr, q, MROWS, D_MODEL, D_MODEL, 0);
    sgemm_bias_kernel<<<gb, 256>>>(e, Wk, bk, nullptr, k, MROWS, D_MODEL, D_MODEL, 0);
    sgemm_bias_kernel<<<gb, 256>>>(e, Wv, bv, nullptr, v, MROWS, D_MODEL, D_MODEL, 0);
    // ctx = softmax(qk^T/sqrt(hd)) v
    attn_kernel<<<dim3(SEQ / 64, BATCH * NHEAD), 256, ATTN_SMEM>>>(q, k, v, ctx);
    // mha = e + ctx @ W0 + b0
    sgemm_bias_kernel<<<gb, 256>>>(ctx, W0, b0, e, mha, MROWS, D_MODEL, D_MODEL, 0);
    // h1 = relu(mha @ W1 + b1)
    sgemm_bias_kernel<<<gb, 256>>>(mha, W1, b1, nullptr, h1, MROWS, D_MODEL, D_MODEL, 1);
    // out = mha + h1 @ W2 + b2
    sgemm_bias_kernel<<<gb, 256>>>(h1, W2, b2, mha, out, MROWS, D_MODEL, D_MODEL, 0);
}

// round 7
// speedup vs baseline: 1.4627x; 1.4627x over previous
#include <cuda_runtime.h>
#include <cuda_bf16.h>
#include <cstdint>

#define MROWS  4096
#define DMODEL 1024
#define DIN    512
#define NHEAD  16
#define SEQ    2048

// ---------------- scratch (allocation-free) ----------------
__device__ __align__(128) float g_e  [MROWS*DMODEL];
__device__ __align__(128) float g_q  [MROWS*DMODEL];
__device__ __align__(128) float g_k  [MROWS*DMODEL];
__device__ __align__(128) float g_v  [MROWS*DMODEL];
__device__ __align__(128) float g_mha[MROWS*DMODEL];
__device__ __align__(128) __nv_bfloat16 g_xh[MROWS*DIN],    g_xl[MROWS*DIN];
__device__ __align__(128) __nv_bfloat16 g_eh[MROWS*DMODEL], g_el[MROWS*DMODEL];
__device__ __align__(128) __nv_bfloat16 g_ch[MROWS*DMODEL], g_cl[MROWS*DMODEL];
__device__ __align__(128) __nv_bfloat16 g_mh[MROWS*DMODEL], g_ml[MROWS*DMODEL];
__device__ __align__(128) __nv_bfloat16 g_hh[MROWS*DMODEL], g_hl[MROWS*DMODEL];
#define WSZ_E (DMODEL*DIN)
#define WSZ   (DMODEL*DMODEL)
__device__ __align__(128) __nv_bfloat16 g_Wth[WSZ_E + 6*WSZ];
__device__ __align__(128) __nv_bfloat16 g_Wtl[WSZ_E + 6*WSZ];

// ---------------- helpers ----------------
__device__ __forceinline__ uint32_t smem_u32(const void* p) {
    uint32_t a;
    asm("{ .reg .u64 t; cvta.to.shared.u64 t, %1; cvt.u32.u64 %0, t; }" : "=r"(a) : "l"(p));
    return a;
}

#define CP_ASYNC16(dst, src) \
    asm volatile("cp.async.cg.shared.global [%0], [%1], 16;" :: "r"(dst), "l"(src) : "memory")
#define CP_COMMIT()  asm volatile("cp.async.commit_group;" ::: "memory")
#define CP_WAIT1()   asm volatile("cp.async.wait_group 1;" ::: "memory")
#define CP_WAIT0()   asm volatile("cp.async.wait_group 0;" ::: "memory")

#define LDSM4(r0, r1, r2, r3, a) \
    asm volatile("ldmatrix.sync.aligned.m8n8.x4.shared.b16 {%0,%1,%2,%3}, [%4];" \
                 : "=r"(r0), "=r"(r1), "=r"(r2), "=r"(r3) : "r"(a))

#define MMA16816(d, a, b) \
    asm volatile("mma.sync.aligned.m16n8k16.row.col.f32.bf16.bf16.f32 " \
                 "{%0,%1,%2,%3}, {%4,%5,%6,%7}, {%8,%9}, {%0,%1,%2,%3};" \
                 : "+f"((d)[0]), "+f"((d)[1]), "+f"((d)[2]), "+f"((d)[3]) \
                 : "r"((a)[0]), "r"((a)[1]), "r"((a)[2]), "r"((a)[3]), \
                   "r"((b)[0]), "r"((b)[1]))

// ============================================================================
// Weight transpose + bf16 hi/lo split: W[K][N] fp32 -> Th/Tl[N][K] bf16
// ============================================================================
__global__ void __launch_bounds__(256)
wsplit(const float* __restrict__ W, __nv_bfloat16* __restrict__ Th,
       __nv_bfloat16* __restrict__ Tl, int K, int N)
{
    __shared__ float t[32][33];
    const int tx = threadIdx.x, ty = threadIdx.y;
    const int n = blockIdx.x * 32 + tx;
#pragma unroll
    for (int i = 0; i < 4; i++) {
        const int k = blockIdx.y * 32 + ty + i * 8;
        t[ty + i * 8][tx] = W[(size_t)k * N + n];
    }
    __syncthreads();
    const int k2 = blockIdx.y * 32 + tx;
#pragma unroll
    for (int i = 0; i < 4; i++) {
        const int n2 = blockIdx.x * 32 + ty + i * 8;
        const float v = t[tx][ty + i * 8];
        const __nv_bfloat16 h = __float2bfloat16(v);
        const __nv_bfloat16 l = __float2bfloat16(v - __bfloat162float(h));
        Th[(size_t)n2 * K + k2] = h;
        Tl[(size_t)n2 * K + k2] = l;
    }
}

__global__ void __launch_bounds__(256)
xsplit(const float* __restrict__ X, __nv_bfloat16* __restrict__ H,
       __nv_bfloat16* __restrict__ L)
{
    const int i = blockIdx.x * 256 + threadIdx.x;
    const float2 v = ((const float2*)X)[i];
    const __nv_bfloat16 hx = __float2bfloat16(v.x);
    const __nv_bfloat16 hy = __float2bfloat16(v.y);
    __nv_bfloat162 hp, lp;
    hp.x = hx; hp.y = hy;
    lp.x = __float2bfloat16(v.x - __bfloat162float(hx));
    lp.y = __float2bfloat16(v.y - __bfloat162float(hy));
    ((__nv_bfloat162*)H)[i] = hp;
    ((__nv_bfloat162*)L)[i] = lp;
}

// ============================================================================
// mma.sync (HMMA) GEMM, bf16 hi/lo split: C = A@B^T with Bt[N][K].
// 128x128 tile, BK=32, 8 warps (4m x 2n), warp tile 32x64.
// Double-buffered cp.async smem tiles [128][40] bf16 (conflict-free LDSM).
// Fused bias / relu / residual; fp32 and/or bf16 hi-lo outputs. N == DMODEL.
// ============================================================================
#define GTILE  10240              // 128*40*2 bytes
#define GBUF   (4*GTILE)          // Ah, Al, Bh, Bl
#define GEMM_SMEM (2*GBUF)        // 81920

__global__ void __launch_bounds__(256)
gemm_mma(const __nv_bfloat16* __restrict__ Ah, const __nv_bfloat16* __restrict__ Al,
         const __nv_bfloat16* __restrict__ Bh, const __nv_bfloat16* __restrict__ Bl,
         const float* __restrict__ bias, const float* __restrict__ res,
         float* __restrict__ Cf, __nv_bfloat16* __restrict__ Ch,
         __nv_bfloat16* __restrict__ Cl, int K, int relu)
{
    extern __shared__ char smem[];
    const uint32_t sb = smem_u32(smem);
    const int tid  = threadIdx.x;
    const int wid  = tid >> 5;
    const int lane = tid & 31;
    const int wm = wid >> 1;          // 0..3
    const int wn = wid & 1;           // 0..1
    const int m0 = blockIdx.y * 128;
    const int n0 = blockIdx.x * 128;

    const __nv_bfloat16* srcs[4] = {
        Ah + (size_t)m0 * K, Al + (size_t)m0 * K,
        Bh + (size_t)n0 * K, Bl + (size_t)n0 * K };

    float acc[2][8][4];
#pragma unroll
    for (int mf = 0; mf < 2; mf++)
#pragma unroll
        for (int nf = 0; nf < 8; nf++)
#pragma unroll
            for (int j = 0; j < 4; j++) acc[mf][nf][j] = 0.f;

    const int NIT = K >> 5;
    const int lrow = tid >> 1;              // 0..127  (2 chunks per row per thread pair)
    const int lc16 = (tid & 1) << 1;        // 0 or 2  (two 16B chunks each)

    // ---- issue loads for iteration 'it' into buffer it&1 ----
    auto issue = [&](int it) {
        const int k0 = it << 5;
        const uint32_t db = sb + (uint32_t)(it & 1) * GBUF;
#pragma unroll
        for (int t = 0; t < 4; t++) {
#pragma unroll
            for (int s = 0; s < 2; s++) {
                const int c16 = lc16 + s;                       // 0..3
                const __nv_bfloat16* g = srcs[t] + (size_t)lrow * K + k0 + c16 * 8;
                const uint32_t d = db + (uint32_t)t * GTILE + (uint32_t)(lrow * 80 + c16 * 16);
                CP_ASYNC16(d, g);
            }
        }
        CP_COMMIT();
    };

    issue(0);

    const int a_r  = lane & 15;
    const int a_kh = lane >> 4;
    const int b_nl = (lane & 7) + ((lane >> 4) << 3);
    const int b_kh = (lane >> 3) & 1;

    for (int it = 0; it < NIT; it++) {
        if (it + 1 < NIT) { issue(it + 1); CP_WAIT1(); }
        else              { CP_WAIT0(); }
        __syncthreads();

        const uint32_t db = sb + (uint32_t)(it & 1) * GBUF;
#pragma unroll
        for (int ks = 0; ks < 2; ks++) {
            uint32_t ah[2][4], al[2][4], bh[8][2], bl[8][2];
#pragma unroll
            for (int mf = 0; mf < 2; mf++) {
                const uint32_t aoff = (uint32_t)((wm * 32 + mf * 16 + a_r) * 80
                                               + (ks * 16 + a_kh * 8) * 2);
                LDSM4(ah[mf][0], ah[mf][1], ah[mf][2], ah[mf][3], db + aoff);
                LDSM4(al[mf][0], al[mf][1], al[mf][2], al[mf][3], db + GTILE + aoff);
            }
#pragma unroll
            for (int nf2 = 0; nf2 < 4; nf2++) {
                const uint32_t boff = (uint32_t)((wn * 64 + nf2 * 16 + b_nl) * 80
                                               + (ks * 16 + b_kh * 8) * 2);
                LDSM4(bh[2*nf2][0], bh[2*nf2][1], bh[2*nf2+1][0], bh[2*nf2+1][1],
                      db + 2u*GTILE + boff);
                LDSM4(bl[2*nf2][0], bl[2*nf2][1], bl[2*nf2+1][0], bl[2*nf2+1][1],
                      db + 3u*GTILE + boff);
            }
#pragma unroll
            for (int mf = 0; mf < 2; mf++)
#pragma unroll
                for (int nf = 0; nf < 8; nf++) {
                    MMA16816(acc[mf][nf], ah[mf], bh[nf]);
                    MMA16816(acc[mf][nf], ah[mf], bl[nf]);
                    MMA16816(acc[mf][nf], al[mf], bh[nf]);
                }
        }
        __syncthreads();
    }

    // ---- epilogue ----
    const int g  = lane >> 2;
    const int i2 = (lane & 3) << 1;
#pragma unroll
    for (int mf = 0; mf < 2; mf++) {
        const int rowa = m0 + wm * 32 + mf * 16 + g;
        const int rowb = rowa + 8;
#pragma unroll
        for (int nf = 0; nf < 8; nf++) {
            const int col = n0 + wn * 64 + nf * 8 + i2;
            const float2 b2 = *(const float2*)&bias[col];
            float v0 = acc[mf][nf][0] + b2.x;
            float v1 = acc[mf][nf][1] + b2.y;
            float v2 = acc[mf][nf][2] + b2.x;
            float v3 = acc[mf][nf][3] + b2.y;
            if (relu) {
                v0 = fmaxf(v0, 0.f); v1 = fmaxf(v1, 0.f);
                v2 = fmaxf(v2, 0.f); v3 = fmaxf(v3, 0.f);
            }
            if (res) {
                const float2 ra = *(const float2*)&res[(size_t)rowa * DMODEL + col];
                const float2 rb = *(const float2*)&res[(size_t)rowb * DMODEL + col];
                v0 += ra.x; v1 += ra.y; v2 += rb.x; v3 += rb.y;
            }
            if (Cf) {
                *(float2*)&Cf[(size_t)rowa * DMODEL + col] = make_float2(v0, v1);
                *(float2*)&Cf[(size_t)rowb * DMODEL + col] = make_float2(v2, v3);
            }
            if (Ch) {
                __nv_bfloat162 hp, lp;
                hp.x = __float2bfloat16(v0); hp.y = __float2bfloat16(v1);
                lp.x = __float2bfloat16(v0 - __bfloat162float(hp.x));
                lp.y = __float2bfloat16(v1 - __bfloat162float(hp.y));
                *(__nv_bfloat162*)&Ch[(size_t)rowa * DMODEL + col] = hp;
                *(__nv_bfloat162*)&Cl[(size_t)rowa * DMODEL + col] = lp;
                hp.x = __float2bfloat16(v2); hp.y = __float2bfloat16(v3);
                lp.x = __float2bfloat16(v2 - __bfloat162float(hp.x));
                lp.y = __float2bfloat16(v3 - __bfloat162float(hp.y));
                *(__nv_bfloat162*)&Ch[(size_t)rowb * DMODEL + col] = hp;
                *(__nv_bfloat162*)&Cl[(size_t)rowb * DMODEL + col] = lp;
            }
        }
    }
}

// ============================================================================
// Flash attention (fp32, non-causal), float4-vectorized smem, bf16 hi/lo out.
// ============================================================================
#define AP 68
#define ATTN_SMEM (4 * 64 * AP * sizeof(float))

__global__ void __launch_bounds__(256)
attn_kernel(const float* __restrict__ Q, const float* __restrict__ K,
            const float* __restrict__ V, __nv_bfloat16* __restrict__ Oh,
            __nv_bfloat16* __restrict__ Ol)
{
    extern __shared__ float sm[];
    float (*Qs)[AP]  = (float(*)[AP])(sm);
    float (*Ks)[AP]  = (float(*)[AP])(sm + 64 * AP);
    float (*Vst)[AP] = (float(*)[AP])(sm + 2 * 64 * AP);
    float (*Ps)[AP]  = (float(*)[AP])(sm + 3 * 64 * AP);

    const int tid  = threadIdx.x;
    const int warp = tid >> 5;
    const int lane = tid & 31;
    const int q0   = blockIdx.x * 64;
    const int bh   = blockIdx.y;
    const int b    = bh >> 4;
    const int h    = bh & (NHEAD - 1);
    const size_t base = (size_t)b * SEQ * DMODEL + (size_t)h * 64;
    const float scale = 0.125f;

#pragma unroll
    for (int s = 0; s < 4; s++) {
        const int id = tid + s * 256;
        const int r = id >> 4;
        const int c = (id & 15) << 2;
        *(float4*)&Qs[r][c] = *(const float4*)&Q[base + (size_t)(q0 + r) * DMODEL + c];
    }

    const int r0 = warp * 8;
    float m_r[8], l_r[8], o0[8], o1[8];
#pragma unroll
    for (int r = 0; r < 8; r++) { m_r[r] = -1e30f; l_r[r] = 0.f; o0[r] = 0.f; o1[r] = 0.f; }

    for (int kv0 = 0; kv0 < SEQ; kv0 += 64) {
#pragma unroll
        for (int s = 0; s < 4; s++) {
            const int id = tid + s * 256;
            const int r = id >> 4;
            const int c = (id & 15) << 2;
            const size_t gg = base + (size_t)(kv0 + r) * DMODEL + c;
            *(float4*)&Ks[r][c] = *(const float4*)&K[gg];
            const float4 vt = *(const float4*)&V[gg];
            Vst[c + 0][r] = vt.x; Vst[c + 1][r] = vt.y;
            Vst[c + 2][r] = vt.z; Vst[c + 3][r] = vt.w;
        }
        __syncthreads();

        float s0[8], s1[8];
#pragma unroll
        for (int r = 0; r < 8; r++) { s0[r] = 0.f; s1[r] = 0.f; }
#pragma unroll
        for (int d4 = 0; d4 < 16; d4++) {
            const float4 k0v = *(const float4*)&Ks[lane][d4 * 4];
            const float4 k1v = *(const float4*)&Ks[lane + 32][d4 * 4];
#pragma unroll
            for (int r = 0; r < 8; r++) {
                const float4 qv = *(const float4*)&Qs[r0 + r][d4 * 4];
                s0[r] = fmaf(qv.x, k0v.x, fmaf(qv.y, k0v.y, fmaf(qv.z, k0v.z, fmaf(qv.w, k0v.w, s0[r]))));
                s1[r] = fmaf(qv.x, k1v.x, fmaf(qv.y, k1v.y, fmaf(qv.z, k1v.z, fmaf(qv.w, k1v.w, s1[r]))));
            }
        }

#pragma unroll
        for (int r = 0; r < 8; r++) {
            const float sv0 = s0[r] * scale;
            const float sv1 = s1[r] * scale;
            float mx = fmaxf(sv0, sv1);
#pragma unroll
            for (int off = 16; off; off >>= 1)
                mx = fmaxf(mx, __shfl_xor_sync(0xffffffffu, mx, off));
            const float mnew  = fmaxf(m_r[r], mx);
            const float alpha = __expf(m_r[r] - mnew);
            const float p0 = __expf(sv0 - mnew);
            const float p1 = __expf(sv1 - mnew);
            float sum = p0 + p1;
#pragma unroll
            for (int off = 16; off; off >>= 1)
                sum += __shfl_xor_sync(0xffffffffu, sum, off);
            l_r[r] = l_r[r] * alpha + sum;
            m_r[r] = mnew;
            o0[r] *= alpha;
            o1[r] *= alpha;
            Ps[r0 + r][lane]      = p0;
            Ps[r0 + r][lane + 32] = p1;
        }
        __syncwarp();

#pragma unroll
        for (int c4 = 0; c4 < 16; c4++) {
            const float4 v0 = *(const float4*)&Vst[lane][c4 * 4];
            const float4 v1 = *(const float4*)&Vst[lane + 32][c4 * 4];
#pragma unroll
            for (int r = 0; r < 8; r++) {
                const float4 p = *(const float4*)&Ps[r0 + r][c4 * 4];
                o0[r] = fmaf(p.x, v0.x, fmaf(p.y, v0.y, fmaf(p.z, v0.z, fmaf(p.w, v0.w, o0[r]))));
                o1[r] = fmaf(p.x, v1.x, fmaf(p.y, v1.y, fmaf(p.z, v1.z, fmaf(p.w, v1.w, o1[r]))));
            }
        }
        __syncthreads();
    }

#pragma unroll
    for (int r = 0; r < 8; r++) {
        const float inv = 1.f / l_r[r];
        const float va = o0[r] * inv;
        const float vb = o1[r] * inv;
        const size_t gg = base + (size_t)(q0 + r0 + r) * DMODEL;
        const __nv_bfloat16 ha = __float2bfloat16(va);
        const __nv_bfloat16 hb = __float2bfloat16(vb);
        Oh[gg + lane]      = ha;
        Oh[gg + lane + 32] = hb;
        Ol[gg + lane]      = __float2bfloat16(va - __bfloat162float(ha));
        Ol[gg + lane + 32] = __float2bfloat16(vb - __bfloat162float(hb));
    }
}

// ============================================================================
// kernel_launch
// ============================================================================
extern "C" void kernel_launch(void* const* d_in, const int* in_sizes, int n_in,
                              void* d_out, int out_size)
{
    (void)in_sizes; (void)n_in; (void)out_size;

    const float* x  = (const float*)d_in[0];
    const float* We = (const float*)d_in[1];
    const float* be = (const float*)d_in[2];
    const float* Wq = (const float*)d_in[3];
    const float* bq = (const float*)d_in[4];
    const float* Wk = (const float*)d_in[5];
    const float* bk = (const float*)d_in[6];
    const float* Wv = (const float*)d_in[7];
    const float* bv = (const float*)d_in[8];
    const float* W0 = (const float*)d_in[9];
    const float* b0 = (const float*)d_in[10];
    const float* W1 = (const float*)d_in[11];
    const float* b1 = (const float*)d_in[12];
    const float* W2 = (const float*)d_in[13];
    const float* b2 = (const float*)d_in[14];
    float* out = (float*)d_out;

    float *e, *q, *k, *v, *mha;
    __nv_bfloat16 *xh, *xl, *eh, *el, *ch, *cl, *mh, *ml, *hh, *hl, *Wth, *Wtl;
    cudaGetSymbolAddress((void**)&e,   g_e);
    cudaGetSymbolAddress((void**)&q,   g_q);
    cudaGetSymbolAddress((void**)&k,   g_k);
    cudaGetSymbolAddress((void**)&v,   g_v);
    cudaGetSymbolAddress((void**)&mha, g_mha);
    cudaGetSymbolAddress((void**)&xh,  g_xh);
    cudaGetSymbolAddress((void**)&xl,  g_xl);
    cudaGetSymbolAddress((void**)&eh,  g_eh);
    cudaGetSymbolAddress((void**)&el,  g_el);
    cudaGetSymbolAddress((void**)&ch,  g_ch);
    cudaGetSymbolAddress((void**)&cl,  g_cl);
    cudaGetSymbolAddress((void**)&mh,  g_mh);
    cudaGetSymbolAddress((void**)&ml,  g_ml);
    cudaGetSymbolAddress((void**)&hh,  g_hh);
    cudaGetSymbolAddress((void**)&hl,  g_hl);
    cudaGetSymbolAddress((void**)&Wth, g_Wth);
    cudaGetSymbolAddress((void**)&Wtl, g_Wtl);

    cudaFuncSetAttribute(gemm_mma, cudaFuncAttributeMaxDynamicSharedMemorySize, GEMM_SMEM);
    cudaFuncSetAttribute(attn_kernel, cudaFuncAttributeMaxDynamicSharedMemorySize, (int)ATTN_SMEM);

    // weight transpose + split
    const dim3 wb(32, 8);
    wsplit<<<dim3(32, 16), wb>>>(We, Wth, Wtl, DIN, DMODEL);
    const float* Ws[6] = { Wq, Wk, Wv, W0, W1, W2 };
    for (int i = 0; i < 6; i++)
        wsplit<<<dim3(32, 32), wb>>>(Ws[i], Wth + WSZ_E + (size_t)i * WSZ,
                                     Wtl + WSZ_E + (size_t)i * WSZ, DMODEL, DMODEL);
    xsplit<<<MROWS * DIN / 512, 256>>>(x, xh, xl);

    const dim3 gg(8, 32);   // (N/128, M/128)
    __nv_bfloat16* Wqh = Wth + WSZ_E;  __nv_bfloat16* Wql = Wtl + WSZ_E;
    __nv_bfloat16* Wkh = Wqh + WSZ;    __nv_bfloat16* Wkl = Wql + WSZ;
    __nv_bfloat16* Wvh = Wkh + WSZ;    __nv_bfloat16* Wvl = Wkl + WSZ;
    __nv_bfloat16* W0h = Wvh + WSZ;    __nv_bfloat16* W0l = Wvl + WSZ;
    __nv_bfloat16* W1h = W0h + WSZ;    __nv_bfloat16* W1l = W0l + WSZ;
    __nv_bfloat16* W2h = W1h + WSZ;    __nv_bfloat16* W2l = W1l + WSZ;

    // e = x @ We + be  (fp32 + hi/lo)
    gemm_mma<<<gg, 256, GEMM_SMEM>>>(xh, xl, Wth, Wtl, be, nullptr, e, eh, el, DIN, 0);
    // q/k/v = e @ W + b (fp32 only)
    gemm_mma<<<gg, 256, GEMM_SMEM>>>(eh, el, Wqh, Wql, bq, nullptr, q, nullptr, nullptr, DMODEL, 0);
    gemm_mma<<<gg, 256, GEMM_SMEM>>>(eh, el, Wkh, Wkl, bk, nullptr, k, nullptr, nullptr, DMODEL, 0);
    gemm_mma<<<gg, 256, GEMM_SMEM>>>(eh, el, Wvh, Wvl, bv, nullptr, v, nullptr, nullptr, DMODEL, 0);
    // attention -> ctx (bf16 hi/lo)
    attn_kernel<<<dim3(SEQ / 64, 32), 256, ATTN_SMEM>>>(q, k, v, ch, cl);
    // mha = e + ctx @ W0 + b0  (fp32 + hi/lo)
    gemm_mma<<<gg, 256, GEMM_SMEM>>>(ch, cl, W0h, W0l, b0, e, mha, mh, ml, DMODEL, 0);
    // h1 = relu(mha @ W1 + b1)  (hi/lo only)
    gemm_mma<<<gg, 256, GEMM_SMEM>>>(mh, ml, W1h, W1l, b1, nullptr, nullptr, hh, hl, DMODEL, 1);
    // out = mha + h1 @ W2 + b2  (fp32)
    gemm_mma<<<gg, 256, GEMM_SMEM>>>(hh, hl, W2h, W2l, b2, mha, out, nullptr, nullptr, DMODEL, 0);
}

// round 9
// speedup vs baseline: 2.5649x; 1.7535x over previous
#include <cuda_runtime.h>
#include <cuda_bf16.h>
#include <cstdint>

#define MROWS  4096
#define DMODEL 1024
#define DIN    512
#define NHEAD  16
#define SEQ    2048

// ---------------- scratch (allocation-free) ----------------
__device__ __align__(128) float g_e  [MROWS*DMODEL];
__device__ __align__(128) float g_mha[MROWS*DMODEL];
__device__ __align__(128) __nv_bfloat16 g_xh[MROWS*DIN],    g_xl[MROWS*DIN];
__device__ __align__(128) __nv_bfloat16 g_eh[MROWS*DMODEL], g_el[MROWS*DMODEL];
__device__ __align__(128) __nv_bfloat16 g_qh[MROWS*DMODEL], g_ql[MROWS*DMODEL];
__device__ __align__(128) __nv_bfloat16 g_kh[MROWS*DMODEL], g_kl[MROWS*DMODEL];
__device__ __align__(128) __nv_bfloat16 g_vh[MROWS*DMODEL], g_vl[MROWS*DMODEL];
__device__ __align__(128) __nv_bfloat16 g_ch[MROWS*DMODEL], g_cl[MROWS*DMODEL];
__device__ __align__(128) __nv_bfloat16 g_mh[MROWS*DMODEL], g_ml[MROWS*DMODEL];
__device__ __align__(128) __nv_bfloat16 g_hh[MROWS*DMODEL], g_hl[MROWS*DMODEL];
#define WSZ_E (DMODEL*DIN)
#define WSZ   (DMODEL*DMODEL)
__device__ __align__(128) __nv_bfloat16 g_Wth[WSZ_E + 6*WSZ];
__device__ __align__(128) __nv_bfloat16 g_Wtl[WSZ_E + 6*WSZ];

// ---------------- helpers ----------------
__device__ __forceinline__ uint32_t smem_u32(const void* p) {
    uint32_t a;
    asm("{ .reg .u64 t; cvta.to.shared.u64 t, %1; cvt.u32.u64 %0, t; }" : "=r"(a) : "l"(p));
    return a;
}

#define CP_ASYNC16(dst, src) \
    asm volatile("cp.async.cg.shared.global [%0], [%1], 16;" :: "r"(dst), "l"(src) : "memory")
#define CP_COMMIT()  asm volatile("cp.async.commit_group;" ::: "memory")
#define CP_WAIT1()   asm volatile("cp.async.wait_group 1;" ::: "memory")
#define CP_WAIT0()   asm volatile("cp.async.wait_group 0;" ::: "memory")

#define LDSM4(r0, r1, r2, r3, a) \
    asm volatile("ldmatrix.sync.aligned.m8n8.x4.shared.b16 {%0,%1,%2,%3}, [%4];" \
                 : "=r"(r0), "=r"(r1), "=r"(r2), "=r"(r3) : "r"(a))
#define LDSM4T(r0, r1, r2, r3, a) \
    asm volatile("ldmatrix.sync.aligned.m8n8.x4.trans.shared.b16 {%0,%1,%2,%3}, [%4];" \
                 : "=r"(r0), "=r"(r1), "=r"(r2), "=r"(r3) : "r"(a))

#define MMA16816(d, a, b) \
    asm volatile("mma.sync.aligned.m16n8k16.row.col.f32.bf16.bf16.f32 " \
                 "{%0,%1,%2,%3}, {%4,%5,%6,%7}, {%8,%9}, {%0,%1,%2,%3};" \
                 : "+f"((d)[0]), "+f"((d)[1]), "+f"((d)[2]), "+f"((d)[3]) \
                 : "r"((a)[0]), "r"((a)[1]), "r"((a)[2]), "r"((a)[3]), \
                   "r"((b)[0]), "r"((b)[1]))

__device__ __forceinline__ uint32_t packbf2(float a, float b) {
    __nv_bfloat162 t;
    t.x = __float2bfloat16(a);
    t.y = __float2bfloat16(b);
    return *(uint32_t*)&t;
}

// ============================================================================
// Weight transpose + bf16 hi/lo split: W[K][N] fp32 -> Th/Tl[N][K] bf16
// ============================================================================
__global__ void __launch_bounds__(256)
wsplit(const float* __restrict__ W, __nv_bfloat16* __restrict__ Th,
       __nv_bfloat16* __restrict__ Tl, int K, int N)
{
    __shared__ float t[32][33];
    const int tx = threadIdx.x, ty = threadIdx.y;
    const int n = blockIdx.x * 32 + tx;
#pragma unroll
    for (int i = 0; i < 4; i++) {
        const int k = blockIdx.y * 32 + ty + i * 8;
        t[ty + i * 8][tx] = W[(size_t)k * N + n];
    }
    __syncthreads();
    const int k2 = blockIdx.y * 32 + tx;
#pragma unroll
    for (int i = 0; i < 4; i++) {
        const int n2 = blockIdx.x * 32 + ty + i * 8;
        const float v = t[tx][ty + i * 8];
        const __nv_bfloat16 h = __float2bfloat16(v);
        const __nv_bfloat16 l = __float2bfloat16(v - __bfloat162float(h));
        Th[(size_t)n2 * K + k2] = h;
        Tl[(size_t)n2 * K + k2] = l;
    }
}

__global__ void __launch_bounds__(256)
xsplit(const float* __restrict__ X, __nv_bfloat16* __restrict__ H,
       __nv_bfloat16* __restrict__ L)
{
    const int i = blockIdx.x * 256 + threadIdx.x;
    const float2 v = ((const float2*)X)[i];
    const __nv_bfloat16 hx = __float2bfloat16(v.x);
    const __nv_bfloat16 hy = __float2bfloat16(v.y);
    __nv_bfloat162 hp, lp;
    hp.x = hx; hp.y = hy;
    lp.x = __float2bfloat16(v.x - __bfloat162float(hx));
    lp.y = __float2bfloat16(v.y - __bfloat162float(hy));
    ((__nv_bfloat162*)H)[i] = hp;
    ((__nv_bfloat162*)L)[i] = lp;
}

// ============================================================================
// mma.sync GEMM, bf16 hi/lo split (unchanged from R7 WIN)
// ============================================================================
#define GTILE  10240
#define GBUF   (4*GTILE)
#define GEMM_SMEM (2*GBUF)

__global__ void __launch_bounds__(256)
gemm_mma(const __nv_bfloat16* __restrict__ Ah, const __nv_bfloat16* __restrict__ Al,
         const __nv_bfloat16* __restrict__ Bh, const __nv_bfloat16* __restrict__ Bl,
         const float* __restrict__ bias, const float* __restrict__ res,
         float* __restrict__ Cf, __nv_bfloat16* __restrict__ Ch,
         __nv_bfloat16* __restrict__ Cl, int K, int relu)
{
    extern __shared__ char smem[];
    const uint32_t sb = smem_u32(smem);
    const int tid  = threadIdx.x;
    const int wid  = tid >> 5;
    const int lane = tid & 31;
    const int wm = wid >> 1;
    const int wn = wid & 1;
    const int m0 = blockIdx.y * 128;
    const int n0 = blockIdx.x * 128;

    const __nv_bfloat16* srcs[4] = {
        Ah + (size_t)m0 * K, Al + (size_t)m0 * K,
        Bh + (size_t)n0 * K, Bl + (size_t)n0 * K };

    float acc[2][8][4];
#pragma unroll
    for (int mf = 0; mf < 2; mf++)
#pragma unroll
        for (int nf = 0; nf < 8; nf++)
#pragma unroll
            for (int j = 0; j < 4; j++) acc[mf][nf][j] = 0.f;

    const int NIT = K >> 5;
    const int lrow = tid >> 1;
    const int lc16 = (tid & 1) << 1;

    auto issue = [&](int it) {
        const int k0 = it << 5;
        const uint32_t db = sb + (uint32_t)(it & 1) * GBUF;
#pragma unroll
        for (int t = 0; t < 4; t++) {
#pragma unroll
            for (int s = 0; s < 2; s++) {
                const int c16 = lc16 + s;
                const __nv_bfloat16* g = srcs[t] + (size_t)lrow * K + k0 + c16 * 8;
                const uint32_t d = db + (uint32_t)t * GTILE + (uint32_t)(lrow * 80 + c16 * 16);
                CP_ASYNC16(d, g);
            }
        }
        CP_COMMIT();
    };

    issue(0);

    const int a_r  = lane & 15;
    const int a_kh = lane >> 4;
    const int b_nl = (lane & 7) + ((lane >> 4) << 3);
    const int b_kh = (lane >> 3) & 1;

    for (int it = 0; it < NIT; it++) {
        if (it + 1 < NIT) { issue(it + 1); CP_WAIT1(); }
        else              { CP_WAIT0(); }
        __syncthreads();

        const uint32_t db = sb + (uint32_t)(it & 1) * GBUF;
#pragma unroll
        for (int ks = 0; ks < 2; ks++) {
            uint32_t ah[2][4], al[2][4], bh[8][2], bl[8][2];
#pragma unroll
            for (int mf = 0; mf < 2; mf++) {
                const uint32_t aoff = (uint32_t)((wm * 32 + mf * 16 + a_r) * 80
                                               + (ks * 16 + a_kh * 8) * 2);
                LDSM4(ah[mf][0], ah[mf][1], ah[mf][2], ah[mf][3], db + aoff);
                LDSM4(al[mf][0], al[mf][1], al[mf][2], al[mf][3], db + GTILE + aoff);
            }
#pragma unroll
            for (int nf2 = 0; nf2 < 4; nf2++) {
                const uint32_t boff = (uint32_t)((wn * 64 + nf2 * 16 + b_nl) * 80
                                               + (ks * 16 + b_kh * 8) * 2);
                LDSM4(bh[2*nf2][0], bh[2*nf2][1], bh[2*nf2+1][0], bh[2*nf2+1][1],
                      db + 2u*GTILE + boff);
                LDSM4(bl[2*nf2][0], bl[2*nf2][1], bl[2*nf2+1][0], bl[2*nf2+1][1],
                      db + 3u*GTILE + boff);
            }
#pragma unroll
            for (int mf = 0; mf < 2; mf++)
#pragma unroll
                for (int nf = 0; nf < 8; nf++) {
                    MMA16816(acc[mf][nf], ah[mf], bh[nf]);
                    MMA16816(acc[mf][nf], ah[mf], bl[nf]);
                    MMA16816(acc[mf][nf], al[mf], bh[nf]);
                }
        }
        __syncthreads();
    }

    const int g  = lane >> 2;
    const int i2 = (lane & 3) << 1;
#pragma unroll
    for (int mf = 0; mf < 2; mf++) {
        const int rowa = m0 + wm * 32 + mf * 16 + g;
        const int rowb = rowa + 8;
#pragma unroll
        for (int nf = 0; nf < 8; nf++) {
            const int col = n0 + wn * 64 + nf * 8 + i2;
            const float2 b2 = *(const float2*)&bias[col];
            float v0 = acc[mf][nf][0] + b2.x;
            float v1 = acc[mf][nf][1] + b2.y;
            float v2 = acc[mf][nf][2] + b2.x;
            float v3 = acc[mf][nf][3] + b2.y;
            if (relu) {
                v0 = fmaxf(v0, 0.f); v1 = fmaxf(v1, 0.f);
                v2 = fmaxf(v2, 0.f); v3 = fmaxf(v3, 0.f);
            }
            if (res) {
                const float2 ra = *(const float2*)&res[(size_t)rowa * DMODEL + col];
                const float2 rb = *(const float2*)&res[(size_t)rowb * DMODEL + col];
                v0 += ra.x; v1 += ra.y; v2 += rb.x; v3 += rb.y;
            }
            if (Cf) {
                *(float2*)&Cf[(size_t)rowa * DMODEL + col] = make_float2(v0, v1);
                *(float2*)&Cf[(size_t)rowb * DMODEL + col] = make_float2(v2, v3);
            }
            if (Ch) {
                __nv_bfloat162 hp, lp;
                hp.x = __float2bfloat16(v0); hp.y = __float2bfloat16(v1);
                lp.x = __float2bfloat16(v0 - __bfloat162float(hp.x));
                lp.y = __float2bfloat16(v1 - __bfloat162float(hp.y));
                *(__nv_bfloat162*)&Ch[(size_t)rowa * DMODEL + col] = hp;
                *(__nv_bfloat162*)&Cl[(size_t)rowa * DMODEL + col] = lp;
                hp.x = __float2bfloat16(v2); hp.y = __float2bfloat16(v3);
                lp.x = __float2bfloat16(v2 - __bfloat162float(hp.x));
                lp.y = __float2bfloat16(v3 - __bfloat162float(hp.y));
                *(__nv_bfloat162*)&Ch[(size_t)rowb * DMODEL + col] = hp;
                *(__nv_bfloat162*)&Cl[(size_t)rowb * DMODEL + col] = lp;
            }
        }
    }
}

// ============================================================================
// Tensor-core flash attention. CTA = 128 q-rows of one (b,h); 8 warps x 16 rows.
// Row stride 144 B (= 128 data + 16 pad; 16B-aligned, conflict-free ldmatrix).
// smem: Qh[0,18432) Ql[18432,36864); buf b at 36864 + b*36864:
//       KH,KL,VH,VL each 64*144 = 9216. Total 110592.
// ============================================================================
#define AT_STR    144
#define AT_QTILE  (128*AT_STR)          // 18432
#define AT_KVT    (64*AT_STR)           // 9216
#define AT_BUF    (4*AT_KVT)            // 36864
#define AT_Q      (2*AT_QTILE)          // 36864
#define AT_SMEM   (AT_Q + 2*AT_BUF)     // 110592

__global__ void __launch_bounds__(256, 1)
attn_mma(const __nv_bfloat16* __restrict__ Qh, const __nv_bfloat16* __restrict__ Ql,
         const __nv_bfloat16* __restrict__ Kh, const __nv_bfloat16* __restrict__ Kl,
         const __nv_bfloat16* __restrict__ Vh, const __nv_bfloat16* __restrict__ Vl,
         __nv_bfloat16* __restrict__ Ch, __nv_bfloat16* __restrict__ Cl)
{
    extern __shared__ char smem[];
    const uint32_t sb = smem_u32(smem);
    const int tid  = threadIdx.x;
    const int wid  = tid >> 5;
    const int lane = tid & 31;
    const int q0   = blockIdx.x * 128;
    const int bh   = blockIdx.y;
    const int b    = bh >> 4;
    const int h    = bh & (NHEAD - 1);
    const size_t base = (size_t)b * SEQ * DMODEL + (size_t)h * 64;
    const float scale = 0.125f;

    const __nv_bfloat16* kvs[4] = { Kh + base, Kl + base, Vh + base, Vl + base };

    auto issue = [&](int it) {
        const int kv0 = it << 6;
        const uint32_t db = sb + AT_Q + (uint32_t)(it & 1) * AT_BUF;
#pragma unroll
        for (int t = 0; t < 4; t++) {
#pragma unroll
            for (int s = 0; s < 2; s++) {
                const int id = tid + s * 256;
                const int row = id >> 3, c16 = id & 7;
                const __nv_bfloat16* g = kvs[t] + (size_t)(kv0 + row) * DMODEL + c16 * 8;
                const uint32_t d = db + (uint32_t)t * AT_KVT + (uint32_t)(row * AT_STR + c16 * 16);
                CP_ASYNC16(d, g);
            }
        }
        CP_COMMIT();
    };

    issue(0);

    // Q tile -> smem (hi/lo), 128 rows x 8 chunks
#pragma unroll
    for (int s = 0; s < 4; s++) {
        const int id = tid + s * 256;
        const int row = id >> 3, c16 = id & 7;
        const size_t g = base + (size_t)(q0 + row) * DMODEL + c16 * 8;
        const uint32_t d = (uint32_t)(row * AT_STR + c16 * 16);
        *(uint4*)(smem + d)            = *(const uint4*)(Qh + g);
        *(uint4*)(smem + AT_QTILE + d) = *(const uint4*)(Ql + g);
    }
    __syncthreads();

    // Q A-fragments (persistent): 4 k-steps x 4 regs, hi+lo
    const int tq  = lane & 7;
    const int sel = lane >> 3;
    const int wq0 = wid * 16;
    uint32_t qfh[4][4], qfl[4][4];
    {
        const int arow = wq0 + tq + (sel & 1) * 8;
#pragma unroll
        for (int ks = 0; ks < 4; ks++) {
            const uint32_t a = sb + (uint32_t)(arow * AT_STR + (ks * 16 + (sel >> 1) * 8) * 2);
            LDSM4(qfh[ks][0], qfh[ks][1], qfh[ks][2], qfh[ks][3], a);
            LDSM4(qfl[ks][0], qfl[ks][1], qfl[ks][2], qfl[ks][3], a + AT_QTILE);
        }
    }

    float oacc[8][4];
#pragma unroll
    for (int nf = 0; nf < 8; nf++)
#pragma unroll
        for (int j = 0; j < 4; j++) oacc[nf][j] = 0.f;
    float m0 = -1e30f, m1 = -1e30f, l0 = 0.f, l1 = 0.f;

    const int NIT = SEQ / 64;
    for (int it = 0; it < NIT; it++) {
        if (it + 1 < NIT) { issue(it + 1); CP_WAIT1(); }
        else              { CP_WAIT0(); }
        __syncthreads();
        const uint32_t db = sb + AT_Q + (uint32_t)(it & 1) * AT_BUF;

        // ---- scores ----
        float sacc[8][4];
#pragma unroll
        for (int nf = 0; nf < 8; nf++)
#pragma unroll
            for (int j = 0; j < 4; j++) sacc[nf][j] = 0.f;

        // Kh sweep: QhKh + QlKh
#pragma unroll
        for (int ks = 0; ks < 4; ks++) {
            uint32_t bf[8][2];
#pragma unroll
            for (int p = 0; p < 4; p++) {
                const uint32_t a = db + (uint32_t)(((p * 16) + tq + (sel >> 1) * 8) * AT_STR
                                                 + (ks * 16 + (sel & 1) * 8) * 2);
                LDSM4(bf[2*p][0], bf[2*p][1], bf[2*p+1][0], bf[2*p+1][1], a);
            }
#pragma unroll
            for (int nf = 0; nf < 8; nf++) MMA16816(sacc[nf], qfh[ks], bf[nf]);
#pragma unroll
            for (int nf = 0; nf < 8; nf++) MMA16816(sacc[nf], qfl[ks], bf[nf]);
        }
        // Kl sweep: QhKl
#pragma unroll
        for (int ks = 0; ks < 4; ks++) {
            uint32_t bf[8][2];
#pragma unroll
            for (int p = 0; p < 4; p++) {
                const uint32_t a = db + AT_KVT + (uint32_t)(((p * 16) + tq + (sel >> 1) * 8) * AT_STR
                                                           + (ks * 16 + (sel & 1) * 8) * 2);
                LDSM4(bf[2*p][0], bf[2*p][1], bf[2*p+1][0], bf[2*p+1][1], a);
            }
#pragma unroll
            for (int nf = 0; nf < 8; nf++) MMA16816(sacc[nf], qfh[ks], bf[nf]);
        }

        // ---- online softmax ----
#pragma unroll
        for (int nf = 0; nf < 8; nf++)
#pragma unroll
            for (int j = 0; j < 4; j++) sacc[nf][j] *= scale;

        float mx0 = -1e30f, mx1 = -1e30f;
#pragma unroll
        for (int nf = 0; nf < 8; nf++) {
            mx0 = fmaxf(mx0, fmaxf(sacc[nf][0], sacc[nf][1]));
            mx1 = fmaxf(mx1, fmaxf(sacc[nf][2], sacc[nf][3]));
        }
        mx0 = fmaxf(mx0, __shfl_xor_sync(0xffffffffu, mx0, 1));
        mx0 = fmaxf(mx0, __shfl_xor_sync(0xffffffffu, mx0, 2));
        mx1 = fmaxf(mx1, __shfl_xor_sync(0xffffffffu, mx1, 1));
        mx1 = fmaxf(mx1, __shfl_xor_sync(0xffffffffu, mx1, 2));

        const float mn0 = fmaxf(m0, mx0);
        const float mn1 = fmaxf(m1, mx1);
        const float al0 = __expf(m0 - mn0);
        const float al1 = __expf(m1 - mn1);
        m0 = mn0; m1 = mn1;

        uint32_t ph[4][4], pl[4][4];
        float sum0 = 0.f, sum1 = 0.f;
#pragma unroll
        for (int nf = 0; nf < 8; nf++) {
            const float p0 = __expf(sacc[nf][0] - m0);
            const float p1 = __expf(sacc[nf][1] - m0);
            const float p2 = __expf(sacc[nf][2] - m1);
            const float p3 = __expf(sacc[nf][3] - m1);
            sum0 += p0 + p1;
            sum1 += p2 + p3;
            const int kf = nf >> 1, hf = (nf & 1) * 2;
            const uint32_t h01 = packbf2(p0, p1);
            const uint32_t h23 = packbf2(p2, p3);
            ph[kf][hf]     = h01;
            ph[kf][hf + 1] = h23;
            const __nv_bfloat162 hb01 = *(const __nv_bfloat162*)&h01;
            const __nv_bfloat162 hb23 = *(const __nv_bfloat162*)&h23;
            pl[kf][hf]     = packbf2(p0 - __bfloat162float(hb01.x), p1 - __bfloat162float(hb01.y));
            pl[kf][hf + 1] = packbf2(p2 - __bfloat162float(hb23.x), p3 - __bfloat162float(hb23.y));
        }
        sum0 += __shfl_xor_sync(0xffffffffu, sum0, 1);
        sum0 += __shfl_xor_sync(0xffffffffu, sum0, 2);
        sum1 += __shfl_xor_sync(0xffffffffu, sum1, 1);
        sum1 += __shfl_xor_sync(0xffffffffu, sum1, 2);
        l0 = l0 * al0 + sum0;
        l1 = l1 * al1 + sum1;
#pragma unroll
        for (int nf = 0; nf < 8; nf++) {
            oacc[nf][0] *= al0; oacc[nf][1] *= al0;
            oacc[nf][2] *= al1; oacc[nf][3] *= al1;
        }

        // ---- PV ----
        // Vh sweep: PhVh + PlVh
#pragma unroll
        for (int kst = 0; kst < 4; kst++) {
            uint32_t vf[8][2];
#pragma unroll
            for (int p = 0; p < 4; p++) {
                const uint32_t a = db + 2u * AT_KVT
                    + (uint32_t)((kst * 16 + tq + (sel & 1) * 8) * AT_STR
                               + (p * 16 + (sel >> 1) * 8) * 2);
                LDSM4T(vf[2*p][0], vf[2*p][1], vf[2*p+1][0], vf[2*p+1][1], a);
            }
#pragma unroll
            for (int nf = 0; nf < 8; nf++) MMA16816(oacc[nf], ph[kst], vf[nf]);
#pragma unroll
            for (int nf = 0; nf < 8; nf++) MMA16816(oacc[nf], pl[kst], vf[nf]);
        }
        // Vl sweep: PhVl
#pragma unroll
        for (int kst = 0; kst < 4; kst++) {
            uint32_t vf[8][2];
#pragma unroll
            for (int p = 0; p < 4; p++) {
                const uint32_t a = db + 3u * AT_KVT
                    + (uint32_t)((kst * 16 + tq + (sel & 1) * 8) * AT_STR
                               + (p * 16 + (sel >> 1) * 8) * 2);
                LDSM4T(vf[2*p][0], vf[2*p][1], vf[2*p+1][0], vf[2*p+1][1], a);
            }
#pragma unroll
            for (int nf = 0; nf < 8; nf++) MMA16816(oacc[nf], ph[kst], vf[nf]);
        }
        __syncthreads();
    }

    // ---- epilogue: normalize, write ctx hi/lo ----
    const float inv0 = 1.f / l0;
    const float inv1 = 1.f / l1;
    const int g  = lane >> 2;
    const int i2 = (lane & 3) << 1;
    const int row0 = q0 + wq0 + g;
    const int row1 = row0 + 8;
#pragma unroll
    for (int nf = 0; nf < 8; nf++) {
        const int coff = nf * 8 + i2;
        const float v0 = oacc[nf][0] * inv0;
        const float v1 = oacc[nf][1] * inv0;
        const float v2 = oacc[nf][2] * inv1;
        const float v3 = oacc[nf][3] * inv1;
        __nv_bfloat162 hp, lp;
        hp.x = __float2bfloat16(v0); hp.y = __float2bfloat16(v1);
        lp.x = __float2bfloat16(v0 - __bfloat162float(hp.x));
        lp.y = __float2bfloat16(v1 - __bfloat162float(hp.y));
        *(__nv_bfloat162*)&Ch[base + (size_t)row0 * DMODEL + coff] = hp;
        *(__nv_bfloat162*)&Cl[base + (size_t)row0 * DMODEL + coff] = lp;
        hp.x = __float2bfloat16(v2); hp.y = __float2bfloat16(v3);
        lp.x = __float2bfloat16(v2 - __bfloat162float(hp.x));
        lp.y = __float2bfloat16(v3 - __bfloat162float(hp.y));
        *(__nv_bfloat162*)&Ch[base + (size_t)row1 * DMODEL + coff] = hp;
        *(__nv_bfloat162*)&Cl[base + (size_t)row1 * DMODEL + coff] = lp;
    }
}

// ============================================================================
// kernel_launch
// ============================================================================
extern "C" void kernel_launch(void* const* d_in, const int* in_sizes, int n_in,
                              void* d_out, int out_size)
{
    (void)in_sizes; (void)n_in; (void)out_size;

    const float* x  = (const float*)d_in[0];
    const float* We = (const float*)d_in[1];
    const float* be = (const float*)d_in[2];
    const float* Wq = (const float*)d_in[3];
    const float* bq = (const float*)d_in[4];
    const float* Wk = (const float*)d_in[5];
    const float* bk = (const float*)d_in[6];
    const float* Wv = (const float*)d_in[7];
    const float* bv = (const float*)d_in[8];
    const float* W0 = (const float*)d_in[9];
    const float* b0 = (const float*)d_in[10];
    const float* W1 = (const float*)d_in[11];
    const float* b1 = (const float*)d_in[12];
    const float* W2 = (const float*)d_in[13];
    const float* b2 = (const float*)d_in[14];
    float* out = (float*)d_out;

    float *e, *mha;
    __nv_bfloat16 *xh, *xl, *eh, *el, *qh, *ql, *kh, *kl, *vh, *vl;
    __nv_bfloat16 *ch, *cl, *mh, *ml, *hh, *hl, *Wth, *Wtl;
    cudaGetSymbolAddress((void**)&e,   g_e);
    cudaGetSymbolAddress((void**)&mha, g_mha);
    cudaGetSymbolAddress((void**)&xh,  g_xh);
    cudaGetSymbolAddress((void**)&xl,  g_xl);
    cudaGetSymbolAddress((void**)&eh,  g_eh);
    cudaGetSymbolAddress((void**)&el,  g_el);
    cudaGetSymbolAddress((void**)&qh,  g_qh);
    cudaGetSymbolAddress((void**)&ql,  g_ql);
    cudaGetSymbolAddress((void**)&kh,  g_kh);
    cudaGetSymbolAddress((void**)&kl,  g_kl);
    cudaGetSymbolAddress((void**)&vh,  g_vh);
    cudaGetSymbolAddress((void**)&vl,  g_vl);
    cudaGetSymbolAddress((void**)&ch,  g_ch);
    cudaGetSymbolAddress((void**)&cl,  g_cl);
    cudaGetSymbolAddress((void**)&mh,  g_mh);
    cudaGetSymbolAddress((void**)&ml,  g_ml);
    cudaGetSymbolAddress((void**)&hh,  g_hh);
    cudaGetSymbolAddress((void**)&hl,  g_hl);
    cudaGetSymbolAddress((void**)&Wth, g_Wth);
    cudaGetSymbolAddress((void**)&Wtl, g_Wtl);

    cudaFuncSetAttribute(gemm_mma, cudaFuncAttributeMaxDynamicSharedMemorySize, GEMM_SMEM);
    cudaFuncSetAttribute(attn_mma, cudaFuncAttributeMaxDynamicSharedMemorySize, AT_SMEM);

    // weight transpose + split
    const dim3 wb(32, 8);
    wsplit<<<dim3(32, 16), wb>>>(We, Wth, Wtl, DIN, DMODEL);
    const float* Ws[6] = { Wq, Wk, Wv, W0, W1, W2 };
    for (int i = 0; i < 6; i++)
        wsplit<<<dim3(32, 32), wb>>>(Ws[i], Wth + WSZ_E + (size_t)i * WSZ,
                                     Wtl + WSZ_E + (size_t)i * WSZ, DMODEL, DMODEL);
    xsplit<<<MROWS * DIN / 512, 256>>>(x, xh, xl);

    const dim3 gg(8, 32);
    __nv_bfloat16* Wqh = Wth + WSZ_E;  __nv_bfloat16* Wql = Wtl + WSZ_E;
    __nv_bfloat16* Wkh = Wqh + WSZ;    __nv_bfloat16* Wkl = Wql + WSZ;
    __nv_bfloat16* Wvh = Wkh + WSZ;    __nv_bfloat16* Wvl = Wkl + WSZ;
    __nv_bfloat16* W0h = Wvh + WSZ;    __nv_bfloat16* W0l = Wvl + WSZ;
    __nv_bfloat16* W1h = W0h + WSZ;    __nv_bfloat16* W1l = W0l + WSZ;
    __nv_bfloat16* W2h = W1h + WSZ;    __nv_bfloat16* W2l = W1l + WSZ;

    // e = x @ We + be  (fp32 + hi/lo)
    gemm_mma<<<gg, 256, GEMM_SMEM>>>(xh, xl, Wth, Wtl, be, nullptr, e, eh, el, DIN, 0);
    // q/k/v = e @ W + b  (bf16 hi/lo only)
    gemm_mma<<<gg, 256, GEMM_SMEM>>>(eh, el, Wqh, Wql, bq, nullptr, nullptr, qh, ql, DMODEL, 0);
    gemm_mma<<<gg, 256, GEMM_SMEM>>>(eh, el, Wkh, Wkl, bk, nullptr, nullptr, kh, kl, DMODEL, 0);
    gemm_mma<<<gg, 256, GEMM_SMEM>>>(eh, el, Wvh, Wvl, bv, nullptr, nullptr, vh, vl, DMODEL, 0);
    // attention -> ctx (bf16 hi/lo)
    attn_mma<<<dim3(SEQ / 128, 32), 256, AT_SMEM>>>(qh, ql, kh, kl, vh, vl, ch, cl);
    // mha = e + ctx @ W0 + b0  (fp32 + hi/lo)
    gemm_mma<<<gg, 256, GEMM_SMEM>>>(ch, cl, W0h, W0l, b0, e, mha, mh, ml, DMODEL, 0);
    // h1 = relu(mha @ W1 + b1)  (hi/lo only)
    gemm_mma<<<gg, 256, GEMM_SMEM>>>(mh, ml, W1h, W1l, b1, nullptr, nullptr, hh, hl, DMODEL, 1);
    // out = mha + h1 @ W2 + b2  (fp32)
    gemm_mma<<<gg, 256, GEMM_SMEM>>>(hh, hl, W2h, W2l, b2, mha, out, nullptr, nullptr, DMODEL, 0);
}